// round 8
// baseline (speedup 1.0000x reference)
#include <cuda_runtime.h>
#include <cstdint>

#define Bq 8
#define Cc 256
#define NQ 4096
#define NK 4096
#define KK 8

// Scratch (device globals — no allocation allowed)
__device__ float g_kf_t[(size_t)Bq * NK * Cc];   // key_features transposed [b, m, c]
__device__ float g_qf_t[(size_t)Bq * NQ * Cc];   // query_features transposed [b, n, c]
__device__ int   g_idx[(size_t)Bq * NQ * KK];    // knn indices

// ---------------------------------------------------------------------------
// Transpose [B, C, N] -> [B, N, C]   (N = 4096, C = 256)
// ---------------------------------------------------------------------------
__global__ void transpose_kernel(const float* __restrict__ in, float* __restrict__ out) {
    __shared__ float tile[32][33];
    const int b  = blockIdx.z;
    const int n0 = blockIdx.x * 32;
    const int c0 = blockIdx.y * 32;
    const float* inb  = in  + (size_t)b * Cc * NQ;
    float*       outb = out + (size_t)b * Cc * NQ;
    const int tx = threadIdx.x;   // 0..31
    const int ty = threadIdx.y;   // 0..7
#pragma unroll
    for (int j = 0; j < 32; j += 8)
        tile[ty + j][tx] = inb[(size_t)(c0 + ty + j) * NQ + (n0 + tx)];
    __syncthreads();
#pragma unroll
    for (int j = 0; j < 32; j += 8)
        outb[(size_t)(n0 + ty + j) * Cc + (c0 + tx)] = tile[tx][ty + j];
}

// ---------------------------------------------------------------------------
// kNN: one thread per query, 128 queries per block (grid 256 -> all SMs busy,
// single top-8 transient per thread). Bitwise-verified arithmetic:
//   cross = fma(qz,kz, fma(qy,ky, rn(qx*kx)))   sq/sk same fma-ascending
//   d     = rn(rn(sq - 2*cross) + sk)
// Ties: strict '<' insertion keeps earlier index first (matches top_k).
// ---------------------------------------------------------------------------
#define KCHUNK 2048
#define QPB 128

__global__ void __launch_bounds__(QPB, 4)
knn_kernel(const float* __restrict__ qc, const float* __restrict__ kc) {
    __shared__ float4 skey[KCHUNK];   // 32 KB: (kx, ky, kz, |k|^2)

    const int b  = blockIdx.x / (NQ / QPB);
    const int n0 = (blockIdx.x % (NQ / QPB)) * QPB;
    const int n  = n0 + threadIdx.x;

    const float* kcb = kc + (size_t)b * 3 * NK;
    const float* qcb = qc + (size_t)b * 3 * NQ;

    const float qx = qcb[n];
    const float qy = qcb[NQ + n];
    const float qz = qcb[2 * NQ + n];
    const float sq = fmaf(qz, qz, fmaf(qy, qy, __fmul_rn(qx, qx)));

    float bd[KK];
    int   bi[KK];
#pragma unroll
    for (int j = 0; j < KK; j++) { bd[j] = 3.4e38f; bi[j] = 0; }

    for (int chunk = 0; chunk < NK; chunk += KCHUNK) {
        __syncthreads();
        // stage keys (coalesced per coordinate plane)
        for (int m = threadIdx.x; m < KCHUNK; m += QPB) {
            const int gm = chunk + m;
            const float x = kcb[gm];
            const float y = kcb[NK + gm];
            const float z = kcb[2 * NK + gm];
            const float skk = fmaf(z, z, fmaf(y, y, __fmul_rn(x, x)));
            skey[m] = make_float4(x, y, z, skk);
        }
        __syncthreads();

        for (int m = 0; m < KCHUNK; m += 4) {
#pragma unroll
            for (int u = 0; u < 4; u++) {
                const float4 kv = skey[m + u];            // uniform addr -> broadcast
                const float cross = fmaf(qz, kv.z,
                                    fmaf(qy, kv.y,
                                         __fmul_rn(qx, kv.x)));
                const float t = __fadd_rn(sq, -2.0f * cross);
                const float d = __fadd_rn(t, kv.w);
                if (d < bd[KK - 1]) {                     // rare
                    float cd = d; int ci = chunk + m + u;
#pragma unroll
                    for (int j = 0; j < KK; j++) {
                        const bool sw = cd < bd[j];
                        const float td = bd[j]; const int ti = bi[j];
                        bd[j] = sw ? cd : td;  bi[j] = sw ? ci : ti;
                        cd    = sw ? td : cd;  ci    = sw ? ti : ci;
                    }
                }
            }
        }
    }

    int* o = g_idx + ((size_t)b * NQ + n) * KK;
#pragma unroll
    for (int j = 0; j < KK; j++) o[j] = bi[j];
}

// ---------------------------------------------------------------------------
// Gather + concat (measured 197.6us in R6 — kept verbatim).
// Block = 4 queries x 8 neighbors = 32 slots; stage rows in padded smem,
// write float2-coalesced to out[b, 2C, NQ, K].
// ---------------------------------------------------------------------------
#define NT 4
#define SLOTS (NT * KK)      // 32
#define PADN 257
#define PADQ 260

__global__ void __launch_bounds__(256, 4)
gather_kernel(float* __restrict__ out) {
    __shared__ int   sidx[SLOTS];
    __shared__ float sn[SLOTS * PADN];   // ~32.9 KB
    __shared__ float sq[NT * PADQ];      // ~4.1 KB

    const int b  = blockIdx.x / (NQ / NT);
    const int n0 = (blockIdx.x % (NQ / NT)) * NT;
    const int t  = threadIdx.x;

    if (t < SLOTS)
        sidx[t] = g_idx[((size_t)b * NQ + n0) * KK + t];

    // stage query rows [NT][C]
    for (int i = t; i < NT * Cc; i += 256) {
        const int r = i >> 8;           // /C
        const int c = i & (Cc - 1);
        sq[r * PADQ + c] = g_qf_t[((size_t)b * NQ + n0 + r) * Cc + c];
    }
    __syncthreads();

    // gather neighbor rows: 32 x 1KB coalesced loads
#pragma unroll
    for (int r = 0; r < SLOTS; r++) {
        sn[r * PADN + t] = g_kf_t[((size_t)b * NK + sidx[r]) * Cc + t];
    }
    __syncthreads();

    // write phase: thread handles slot pair (2*sp, 2*sp+1) for channel c
    const int sp = t & 15;              // 0..15 -> slots 2sp, 2sp+1
    const int cg = t >> 4;              // 0..15
    const int s0 = 2 * sp;
    const int nloc = s0 >> 3;           // local query index

#pragma unroll
    for (int ci = 0; ci < 16; ci++) {
        const int c = ci * 16 + cg;
        const float qv  = sq[nloc * PADQ + c];
        const float v0  = sn[s0 * PADN + c];
        const float v1  = sn[(s0 + 1) * PADN + c];

        const size_t baseD = (((size_t)b * (2 * Cc) + c) * NQ + n0) * KK + s0;
        const size_t baseQ = (((size_t)b * (2 * Cc) + Cc + c) * NQ + n0) * KK + s0;
        *reinterpret_cast<float2*>(out + baseD) = make_float2(v0 - qv, v1 - qv);
        *reinterpret_cast<float2*>(out + baseQ) = make_float2(qv, qv);
    }
}

// ---------------------------------------------------------------------------
extern "C" void kernel_launch(void* const* d_in, const int* in_sizes, int n_in,
                              void* d_out, int out_size) {
    const float* query_coords   = (const float*)d_in[0];
    const float* query_features = (const float*)d_in[1];
    const float* key_coords     = (const float*)d_in[2];
    const float* key_features   = (const float*)d_in[3];
    float* out = (float*)d_out;

    float* kf_t; cudaGetSymbolAddress((void**)&kf_t, g_kf_t);
    float* qf_t; cudaGetSymbolAddress((void**)&qf_t, g_qf_t);

    // One-time host-side stream/event setup (outside capture on first call;
    // reused inside capture afterwards). Falls back to single-stream if
    // creation fails.
    static cudaStream_t s2 = 0;
    static cudaEvent_t eFork = 0, eKnn = 0;
    static bool init_done = false;
    if (!init_done) {
        if (cudaStreamCreateWithFlags(&s2, cudaStreamNonBlocking) != cudaSuccess) s2 = 0;
        if (cudaEventCreateWithFlags(&eFork, cudaEventDisableTiming) != cudaSuccess) eFork = 0;
        if (cudaEventCreateWithFlags(&eKnn, cudaEventDisableTiming) != cudaSuccess) eKnn = 0;
        if (!eFork || !eKnn) s2 = 0;   // no fork without events
        init_done = true;
    }

    const bool fork = (s2 != 0);

    if (fork) {
        cudaEventRecord(eFork, 0);
        cudaStreamWaitEvent(s2, eFork, 0);
    }

    // Branch A (default stream): feature transposes
    dim3 tgrid(NQ / 32, Cc / 32, Bq);
    dim3 tblk(32, 8);
    transpose_kernel<<<tgrid, tblk>>>(query_features, qf_t);
    transpose_kernel<<<tgrid, tblk>>>(key_features,   kf_t);

    // Branch B (s2): kNN on coords only
    knn_kernel<<<Bq * (NQ / QPB), QPB, 0, fork ? s2 : 0>>>(query_coords, key_coords);

    if (fork) {
        cudaEventRecord(eKnn, s2);
        cudaStreamWaitEvent(0, eKnn, 0);
    }

    // Join: gather needs transposed features + indices
    gather_kernel<<<Bq * (NQ / NT), 256>>>(out);
}

// round 9
// speedup vs baseline: 1.6407x; 1.6407x over previous
#include <cuda_runtime.h>
#include <cstdint>

#define Bq 8
#define Cc 256
#define NQ 4096
#define NK 4096
#define KK 8

// Scratch (device globals — no allocation allowed)
__device__ float g_kf_t[(size_t)Bq * NK * Cc];   // key_features transposed [b, m, c]
__device__ float g_qf_t[(size_t)Bq * NQ * Cc];   // query_features transposed [b, n, c]
__device__ int   g_idx[(size_t)Bq * NQ * KK];    // knn indices

// ---------------------------------------------------------------------------
// Transpose [B, C, N] -> [B, N, C] for BOTH feature tensors in one launch.
// blockIdx.z: z&7 = batch, z>>3 = which tensor (0 = query, 1 = key).
// ---------------------------------------------------------------------------
__global__ void transpose_kernel(const float* __restrict__ qf,
                                 const float* __restrict__ kf,
                                 float* __restrict__ qf_t,
                                 float* __restrict__ kf_t) {
    __shared__ float tile[32][33];
    const int z  = blockIdx.z;
    const int b  = z & 7;
    const float* in  = (z >> 3) ? kf   : qf;
    float*       out = (z >> 3) ? kf_t : qf_t;
    const int n0 = blockIdx.x * 32;
    const int c0 = blockIdx.y * 32;
    const float* inb  = in  + (size_t)b * Cc * NQ;
    float*       outb = out + (size_t)b * Cc * NQ;
    const int tx = threadIdx.x;   // 0..31
    const int ty = threadIdx.y;   // 0..7
#pragma unroll
    for (int j = 0; j < 32; j += 8)
        tile[ty + j][tx] = inb[(size_t)(c0 + ty + j) * NQ + (n0 + tx)];
    __syncthreads();
#pragma unroll
    for (int j = 0; j < 32; j += 8)
        outb[(size_t)(n0 + ty + j) * Cc + (c0 + tx)] = tile[tx][ty + j];
}

// ---------------------------------------------------------------------------
// kNN (R6 verbatim — bitwise-verified arithmetic, rel_err 0.0):
//   cross = fma(qz,kz, fma(qy,ky, rn(qx*kx)))   sq/sk same fma-ascending
//   d     = rn(rn(sq - 2*cross) + sk)
// Ties: strict '<' insertion keeps earlier index first (matches top_k).
// ---------------------------------------------------------------------------
#define KCHUNK 2048

__global__ void __launch_bounds__(256, 1)
knn_kernel(const float* __restrict__ qc, const float* __restrict__ kc) {
    __shared__ float4 skey[KCHUNK];   // 32 KB: (kx, ky, kz, |k|^2)

    const int b  = blockIdx.x / (NQ / 256);
    const int n0 = (blockIdx.x % (NQ / 256)) * 256;
    const int n  = n0 + threadIdx.x;

    const float* kcb = kc + (size_t)b * 3 * NK;
    const float* qcb = qc + (size_t)b * 3 * NQ;

    const float qx = qcb[n];
    const float qy = qcb[NQ + n];
    const float qz = qcb[2 * NQ + n];
    const float sq = fmaf(qz, qz, fmaf(qy, qy, __fmul_rn(qx, qx)));

    float bd[KK];
    int   bi[KK];
#pragma unroll
    for (int j = 0; j < KK; j++) { bd[j] = 3.4e38f; bi[j] = 0; }

    for (int chunk = 0; chunk < NK; chunk += KCHUNK) {
        __syncthreads();
        for (int m = threadIdx.x; m < KCHUNK; m += 256) {
            const int gm = chunk + m;
            const float x = kcb[gm];
            const float y = kcb[NK + gm];
            const float z = kcb[2 * NK + gm];
            const float skk = fmaf(z, z, fmaf(y, y, __fmul_rn(x, x)));
            skey[m] = make_float4(x, y, z, skk);
        }
        __syncthreads();

        for (int m = 0; m < KCHUNK; m += 4) {
#pragma unroll
            for (int u = 0; u < 4; u++) {
                const float4 kv = skey[m + u];            // uniform addr -> broadcast
                const float cross = fmaf(qz, kv.z,
                                    fmaf(qy, kv.y,
                                         __fmul_rn(qx, kv.x)));
                const float t = __fadd_rn(sq, -2.0f * cross);
                const float d = __fadd_rn(t, kv.w);
                if (d < bd[KK - 1]) {                     // rare
                    float cd = d; int ci = chunk + m + u;
#pragma unroll
                    for (int j = 0; j < KK; j++) {
                        const bool sw = cd < bd[j];
                        const float td = bd[j]; const int ti = bi[j];
                        bd[j] = sw ? cd : td;  bi[j] = sw ? ci : ti;
                        cd    = sw ? td : cd;  ci    = sw ? ti : ci;
                    }
                }
            }
        }
    }

    int* o = g_idx + ((size_t)b * NQ + n) * KK;
#pragma unroll
    for (int j = 0; j < KK; j++) o[j] = bi[j];
}

// ---------------------------------------------------------------------------
// Gather + concat. Block = 4 queries x 8 neighbors = 32 slots.
// Stage 32 neighbor rows + 4 query rows in padded smem, then write with
// STG.128 (slot quads). Bank-verified conflict-free reads.
// occupancy target: 6 blocks/SM (regs <= 42).
// ---------------------------------------------------------------------------
#define NT 4
#define SLOTS (NT * KK)      // 32
#define PADN 257
#define PADQ 260

__global__ void __launch_bounds__(256, 6)
gather_kernel(float* __restrict__ out) {
    __shared__ int   sidx[SLOTS];
    __shared__ float sn[SLOTS * PADN];   // ~32.9 KB
    __shared__ float sq[NT * PADQ];      // ~4.1 KB

    const int b  = blockIdx.x / (NQ / NT);
    const int n0 = (blockIdx.x % (NQ / NT)) * NT;
    const int t  = threadIdx.x;

    if (t < SLOTS)
        sidx[t] = g_idx[((size_t)b * NQ + n0) * KK + t];

    // stage query rows [NT][C]
    for (int i = t; i < NT * Cc; i += 256) {
        const int r = i >> 8;           // /C
        const int c = i & (Cc - 1);
        sq[r * PADQ + c] = g_qf_t[((size_t)b * NQ + n0 + r) * Cc + c];
    }
    __syncthreads();

    // gather neighbor rows: 32 x 1KB coalesced loads
#pragma unroll
    for (int r = 0; r < SLOTS; r++) {
        sn[r * PADN + t] = g_kf_t[((size_t)b * NK + sidx[r]) * Cc + t];
    }
    __syncthreads();

    // write phase: thread owns slot quad q (slots 4q..4q+3, all same query)
    // and channel c = ci*32 + cg. Banks: (4q + j + c) mod 32 -> 4b+a+const,
    // injective over the warp -> conflict-free. STG.128 stores.
    const int q  = t & 7;               // slot quad 0..7
    const int cg = t >> 3;              // 0..31
    const int s0 = 4 * q;
    const int nloc = q >> 1;            // local query index

#pragma unroll
    for (int ci = 0; ci < 8; ci++) {
        const int c = ci * 32 + cg;
        const float qv = sq[nloc * PADQ + c];
        const float v0 = sn[(s0 + 0) * PADN + c];
        const float v1 = sn[(s0 + 1) * PADN + c];
        const float v2 = sn[(s0 + 2) * PADN + c];
        const float v3 = sn[(s0 + 3) * PADN + c];

        const size_t baseD = (((size_t)b * (2 * Cc) + c) * NQ + n0) * KK + s0;
        const size_t baseQ = (((size_t)b * (2 * Cc) + Cc + c) * NQ + n0) * KK + s0;
        *reinterpret_cast<float4*>(out + baseD) =
            make_float4(v0 - qv, v1 - qv, v2 - qv, v3 - qv);
        *reinterpret_cast<float4*>(out + baseQ) = make_float4(qv, qv, qv, qv);
    }
}

// ---------------------------------------------------------------------------
extern "C" void kernel_launch(void* const* d_in, const int* in_sizes, int n_in,
                              void* d_out, int out_size) {
    const float* query_coords   = (const float*)d_in[0];
    const float* query_features = (const float*)d_in[1];
    const float* key_coords     = (const float*)d_in[2];
    const float* key_features   = (const float*)d_in[3];
    float* out = (float*)d_out;

    float* kf_t; cudaGetSymbolAddress((void**)&kf_t, g_kf_t);
    float* qf_t; cudaGetSymbolAddress((void**)&qf_t, g_qf_t);

    dim3 tgrid(NQ / 32, Cc / 32, 2 * Bq);
    dim3 tblk(32, 8);
    transpose_kernel<<<tgrid, tblk>>>(query_features, key_features, qf_t, kf_t);

    knn_kernel<<<Bq * (NQ / 256), 256>>>(query_coords, key_coords);

    gather_kernel<<<Bq * (NQ / NT), 256>>>(out);
}